// round 8
// baseline (speedup 1.0000x reference)
#include <cuda_runtime.h>
#include <math.h>
#include <stdint.h>

// Problem constants
#define BB 2
#define SS 2048
#define HH 2048
#define NH 16
#define HD 128
#define SCALE 0.08838834764831845f  // 1/sqrt(128)

// ---------------- scratch (device globals; no allocation allowed) ----------
__device__ float g_q[(size_t)BB * NH * SS * HD];
__device__ float g_k[(size_t)BB * NH * SS * HD];
__device__ float g_v[(size_t)BB * NH * SS * HD];
__device__ float g_att[(size_t)BB * SS * HH];

// ---------------- 3xTF32 tensor-core GEMM ---------------------------------
// C[m,n] = sum_k A[m,k] * W[n,k]  (NT). BM=BN=128, BK=16, 256 threads.
// 8 warps in 2(m) x 4(n); warp tile 64x32 = 4x4 m16n8k8 mma tiles.
// Split-TF32: x = hi + lo (hi = 10-bit mantissa); A*B ~= AhBh + AhBl + AlBh.
// MODE 0: scatter output into (B, NH, S, HD) layout. MODE 1: row-major.

#define BKT_G 16
#define SPITCH 20   // floats; 20*4=80B row stride: 16B-aligned, conflict-free frags

__device__ __forceinline__ uint32_t tf32_hi_bits(float x) {
    return __float_as_uint(x) & 0xFFFFE000u;
}

__device__ __forceinline__ void mma_tf32(float* c,
                                         const uint32_t* a,
                                         const uint32_t* b) {
    asm volatile(
        "mma.sync.aligned.m16n8k8.row.col.f32.tf32.tf32.f32 "
        "{%0,%1,%2,%3}, {%4,%5,%6,%7}, {%8,%9}, {%0,%1,%2,%3};"
        : "+f"(c[0]), "+f"(c[1]), "+f"(c[2]), "+f"(c[3])
        : "r"(a[0]), "r"(a[1]), "r"(a[2]), "r"(a[3]),
          "r"(b[0]), "r"(b[1]));
}

template <int MODE>
__device__ __forceinline__ void gemm_tf32_body(const float* __restrict__ A,
                                               const float* __restrict__ W,
                                               float* __restrict__ C,
                                               int K, int N) {
    __shared__ float As[2][128][SPITCH];
    __shared__ float Ws[2][128][SPITCH];

    const int bn = blockIdx.x;
    const int bm = blockIdx.y;
    const int t  = threadIdx.x;
    const int wid  = t >> 5;
    const int lane = t & 31;
    const int g  = lane >> 2;    // group 0..7
    const int tg = lane & 3;     // thread-in-group 0..3

    const int wm = (wid & 1) * 64;   // warp m offset in tile
    const int wn = (wid >> 1) * 32;  // warp n offset in tile

    const float* Ablk = A + (size_t)(bm * 128) * K;
    const float* Wblk = W + (size_t)(bn * 128) * K;

    // global staging task: id -> (row, kquad)
    const int r0 = t >> 2;               // 0..63   (id = t)
    const int q0 = (t & 3) * 4;
    const int r1 = (t + 256) >> 2;       // 64..127 (id = t+256)
    const int q1 = (t & 3) * 4;

    float acc[4][4][4];
#pragma unroll
    for (int i = 0; i < 4; i++)
#pragma unroll
        for (int j = 0; j < 4; j++)
#pragma unroll
            for (int r = 0; r < 4; r++) acc[i][j][r] = 0.f;

    // prologue: stage K-tile 0 into buffer 0
    {
        float4 a0 = *(const float4*)(Ablk + (size_t)r0 * K + q0);
        float4 a1 = *(const float4*)(Ablk + (size_t)r1 * K + q1);
        float4 w0 = *(const float4*)(Wblk + (size_t)r0 * K + q0);
        float4 w1 = *(const float4*)(Wblk + (size_t)r1 * K + q1);
        *(float4*)&As[0][r0][q0] = a0;
        *(float4*)&As[0][r1][q1] = a1;
        *(float4*)&Ws[0][r0][q0] = w0;
        *(float4*)&Ws[0][r1][q1] = w1;
    }
    __syncthreads();

    int buf = 0;
    for (int kt = 0; kt < K; kt += BKT_G) {
        const bool has_next = (kt + BKT_G) < K;
        float4 pa0, pa1, pw0, pw1;
        if (has_next) {
            pa0 = *(const float4*)(Ablk + (size_t)r0 * K + kt + BKT_G + q0);
            pa1 = *(const float4*)(Ablk + (size_t)r1 * K + kt + BKT_G + q1);
            pw0 = *(const float4*)(Wblk + (size_t)r0 * K + kt + BKT_G + q0);
            pw1 = *(const float4*)(Wblk + (size_t)r1 * K + kt + BKT_G + q1);
        }

#pragma unroll
        for (int k0 = 0; k0 < BKT_G; k0 += 8) {
            uint32_t Ah[4][4], Al[4][4];
            uint32_t Bh[4][2], Bl[4][2];

#pragma unroll
            for (int i = 0; i < 4; i++) {
                int row = wm + i * 16 + g;
                float f0 = As[buf][row][k0 + tg];
                float f1 = As[buf][row + 8][k0 + tg];
                float f2 = As[buf][row][k0 + tg + 4];
                float f3 = As[buf][row + 8][k0 + tg + 4];
                Ah[i][0] = tf32_hi_bits(f0);
                Ah[i][1] = tf32_hi_bits(f1);
                Ah[i][2] = tf32_hi_bits(f2);
                Ah[i][3] = tf32_hi_bits(f3);
                Al[i][0] = tf32_hi_bits(f0 - __uint_as_float(Ah[i][0]));
                Al[i][1] = tf32_hi_bits(f1 - __uint_as_float(Ah[i][1]));
                Al[i][2] = tf32_hi_bits(f2 - __uint_as_float(Ah[i][2]));
                Al[i][3] = tf32_hi_bits(f3 - __uint_as_float(Ah[i][3]));
            }
#pragma unroll
            for (int j = 0; j < 4; j++) {
                int col = wn + j * 8 + g;
                float f0 = Ws[buf][col][k0 + tg];
                float f1 = Ws[buf][col][k0 + tg + 4];
                Bh[j][0] = tf32_hi_bits(f0);
                Bh[j][1] = tf32_hi_bits(f1);
                Bl[j][0] = tf32_hi_bits(f0 - __uint_as_float(Bh[j][0]));
                Bl[j][1] = tf32_hi_bits(f1 - __uint_as_float(Bh[j][1]));
            }

#pragma unroll
            for (int i = 0; i < 4; i++)
#pragma unroll
                for (int j = 0; j < 4; j++) {
                    mma_tf32(acc[i][j], Ah[i], Bh[j]);
                    mma_tf32(acc[i][j], Ah[i], Bl[j]);
                    mma_tf32(acc[i][j], Al[i], Bh[j]);
                }
        }

        if (has_next) {
            int nb = buf ^ 1;
            *(float4*)&As[nb][r0][q0] = pa0;
            *(float4*)&As[nb][r1][q1] = pa1;
            *(float4*)&Ws[nb][r0][q0] = pw0;
            *(float4*)&Ws[nb][r1][q1] = pw1;
            __syncthreads();
        }
        buf ^= 1;
    }

    // writeback: c0=[g][2t], c1=[g][2t+1], c2=[g+8][2t], c3=[g+8][2t+1]
#pragma unroll
    for (int i = 0; i < 4; i++) {
#pragma unroll
        for (int j = 0; j < 4; j++) {
            int m0 = bm * 128 + wm + i * 16 + g;
            int n0 = bn * 128 + wn + j * 8 + tg * 2;
#pragma unroll
            for (int r = 0; r < 4; r++) {
                int m = m0 + (r >> 1) * 8;
                int n = n0 + (r & 1);
                if (MODE == 0) {
                    int b  = m >> 11;
                    int s  = m & (SS - 1);
                    int nh = n >> 7;
                    int hd = n & (HD - 1);
                    size_t o = ((((size_t)b * NH + nh) << 11) + s) * HD + hd;
                    C[o] = acc[i][j][r];
                } else {
                    C[(size_t)m * N + n] = acc[i][j][r];
                }
            }
        }
    }
}

// Fused QKV projection: grid.z selects which weight/output
__global__ void __launch_bounds__(256) sgemm_qkv(
    const float* __restrict__ A,
    const float* __restrict__ Wq, const float* __restrict__ Wk,
    const float* __restrict__ Wv,
    float* __restrict__ q, float* __restrict__ k, float* __restrict__ v) {
    const float* W = (blockIdx.z == 0) ? Wq : (blockIdx.z == 1) ? Wk : Wv;
    float* C       = (blockIdx.z == 0) ? q  : (blockIdx.z == 1) ? k  : v;
    gemm_tf32_body<0>(A, W, C, HH, HH);
}

__global__ void __launch_bounds__(256) sgemm_out(
    const float* __restrict__ A, const float* __restrict__ W,
    float* __restrict__ C) {
    gemm_tf32_body<1>(A, W, C, HH, HH);
}

// ---------------- RoPE: in-place on q and k (B, NH, S, HD) -----------------
__global__ void __launch_bounds__(256) rope_kernel(
    float* __restrict__ q, float* __restrict__ k,
    const float* __restrict__ cosp, const float* __restrict__ sinp) {
    const int total = BB * NH * SS * (HD / 2);   // pairs per tensor
    int idx = blockIdx.x * blockDim.x + threadIdx.x;
    float* ptr = q;
    if (idx >= total) { idx -= total; ptr = k; }
    if (idx >= total) return;

    int hd = idx & 63;
    int ro = idx >> 6;
    int s  = ro & (SS - 1);
    size_t base = (size_t)ro * HD;

    float x1 = ptr[base + hd];
    float x2 = ptr[base + hd + 64];
    float c1 = cosp[s * HD + hd];
    float s1 = sinp[s * HD + hd];
    float c2 = cosp[s * HD + hd + 64];
    float s2 = sinp[s * HD + hd + 64];
    ptr[base + hd]      = x1 * c1 - x2 * s1;
    ptr[base + hd + 64] = x2 * c2 + x1 * s2;
}

// ---------------- Flash attention (causal, fp32, online softmax) -----------
#define BQ 64
#define BKT 64
#define QPITCH 132
#define PPITCH 68
#define FLASH_SMEM ((2 * BQ * QPITCH + BQ * HD + BQ * PPITCH) * 4)

__global__ void __launch_bounds__(256) flash_kernel(
    const float* __restrict__ q, const float* __restrict__ k,
    const float* __restrict__ v, float* __restrict__ out) {
    extern __shared__ float sm[];
    float* Qs = sm;                        // [64][132]
    float* Ks = Qs + BQ * QPITCH;          // [64][132]
    float* Vs = Ks + BQ * QPITCH;          // [64][128]
    float* Ps = Vs + BQ * HD;              // [64][68]

    const int qt = blockIdx.x;
    const int nh = blockIdx.y;
    const int b  = blockIdx.z;
    const int bh = b * NH + nh;

    const float* qb = q + (size_t)bh * SS * HD;
    const float* kb = k + (size_t)bh * SS * HD;
    const float* vb = v + (size_t)bh * SS * HD;

    const int tid = threadIdx.x;
    const int r   = tid >> 2;
    const int j   = tid & 3;
    const int qg  = qt * BQ + r;

    // load Q tile
    for (int i = tid; i < BQ * HD / 4; i += 256) {
        int row = i / (HD / 4), c4 = i % (HD / 4);
        float4 val = ((const float4*)(qb + (size_t)(qt * BQ + row) * HD))[c4];
        *(float4*)&Qs[row * QPITCH + c4 * 4] = val;
    }

    float m = -INFINITY, l = 0.f;
    float O[32];
#pragma unroll
    for (int i = 0; i < 32; i++) O[i] = 0.f;

    for (int kt = 0; kt <= qt; ++kt) {
        __syncthreads();
        for (int i = tid; i < BKT * HD / 4; i += 256) {
            int row = i / (HD / 4), c4 = i % (HD / 4);
            float4 kk4 = ((const float4*)(kb + (size_t)(kt * BKT + row) * HD))[c4];
            *(float4*)&Ks[row * QPITCH + c4 * 4] = kk4;
            float4 vv4 = ((const float4*)(vb + (size_t)(kt * BKT + row) * HD))[c4];
            *(float4*)&Vs[row * HD + c4 * 4] = vv4;
        }
        __syncthreads();

        float acc[16];
#pragma unroll
        for (int i = 0; i < 16; i++) acc[i] = 0.f;
        for (int d0 = 0; d0 < HD; d0 += 4) {
            float4 qv = *(const float4*)&Qs[r * QPITCH + d0];
#pragma unroll
            for (int cc = 0; cc < 16; ++cc) {
                float4 kv = *(const float4*)&Ks[(j * 16 + cc) * QPITCH + d0];
                acc[cc] += qv.x * kv.x + qv.y * kv.y + qv.z * kv.z + qv.w * kv.w;
            }
        }

        float rowmax = -INFINITY;
#pragma unroll
        for (int cc = 0; cc < 16; ++cc) {
            int kg = kt * BKT + j * 16 + cc;
            float sv = acc[cc] * SCALE;
            if (kg > qg) sv = -INFINITY;
            acc[cc] = sv;
            rowmax = fmaxf(rowmax, sv);
        }
        rowmax = fmaxf(rowmax, __shfl_xor_sync(0xffffffffu, rowmax, 1));
        rowmax = fmaxf(rowmax, __shfl_xor_sync(0xffffffffu, rowmax, 2));

        float mnew = fmaxf(m, rowmax);
        float corr = __expf(m - mnew);
        float rsum = 0.f;
#pragma unroll
        for (int cc = 0; cc < 16; ++cc) {
            float p = __expf(acc[cc] - mnew);
            Ps[r * PPITCH + j * 16 + cc] = p;
            rsum += p;
        }
        rsum += __shfl_xor_sync(0xffffffffu, rsum, 1);
        rsum += __shfl_xor_sync(0xffffffffu, rsum, 2);
        l = l * corr + rsum;
        m = mnew;
#pragma unroll
        for (int i = 0; i < 32; i++) O[i] *= corr;
        __syncwarp();

        for (int kk = 0; kk < BKT; ++kk) {
            float p = Ps[r * PPITCH + kk];
            const float* vrow = &Vs[kk * HD + j * 32];
#pragma unroll
            for (int i2 = 0; i2 < 8; i2++) {
                float4 vv = *(const float4*)&vrow[i2 * 4];
                O[i2 * 4 + 0] += p * vv.x;
                O[i2 * 4 + 1] += p * vv.y;
                O[i2 * 4 + 2] += p * vv.z;
                O[i2 * 4 + 3] += p * vv.w;
            }
        }
        __syncwarp();
    }

    float inv_l = 1.0f / l;
    float* orow = out + ((size_t)(b * SS + qg) * HH) + nh * HD + j * 32;
#pragma unroll
    for (int i2 = 0; i2 < 8; i2++) {
        float4 vv;
        vv.x = O[i2 * 4 + 0] * inv_l;
        vv.y = O[i2 * 4 + 1] * inv_l;
        vv.z = O[i2 * 4 + 2] * inv_l;
        vv.w = O[i2 * 4 + 3] * inv_l;
        *(float4*)&orow[i2 * 4] = vv;
    }
}

// ---------------- launch ---------------------------------------------------
extern "C" void kernel_launch(void* const* d_in, const int* in_sizes, int n_in,
                              void* d_out, int out_size) {
    const float* hs   = (const float*)d_in[0];
    const float* cosp = (const float*)d_in[1];
    const float* sinp = (const float*)d_in[2];
    const float* Wq   = (const float*)d_in[3];
    const float* Wk   = (const float*)d_in[4];
    const float* Wv   = (const float*)d_in[5];
    const float* Wo   = (const float*)d_in[6];
    float* out = (float*)d_out;

    float *qp, *kp, *vp, *ap;
    cudaGetSymbolAddress((void**)&qp, g_q);
    cudaGetSymbolAddress((void**)&kp, g_k);
    cudaGetSymbolAddress((void**)&vp, g_v);
    cudaGetSymbolAddress((void**)&ap, g_att);

    // 1) QKV projections (fused over grid.z)
    dim3 pg(HH / 128, (BB * SS) / 128, 3);
    sgemm_qkv<<<pg, 256>>>(hs, Wq, Wk, Wv, qp, kp, vp);

    // 2) RoPE on q and k
    int pairs = 2 * BB * NH * SS * (HD / 2);
    rope_kernel<<<(pairs + 255) / 256, 256>>>(qp, kp, cosp, sinp);

    // 3) causal flash attention
    cudaFuncSetAttribute(flash_kernel,
                         cudaFuncAttributeMaxDynamicSharedMemorySize,
                         FLASH_SMEM);
    dim3 fg(SS / BQ, NH, BB);
    flash_kernel<<<fg, 256, FLASH_SMEM>>>(qp, kp, vp, ap);

    // 4) output projection
    dim3 og(HH / 128, (BB * SS) / 128, 1);
    sgemm_out<<<og, 256>>>(ap, Wo, out);
}

// round 9
// speedup vs baseline: 3.3857x; 3.3857x over previous
#include <cuda_runtime.h>
#include <math.h>
#include <stdint.h>

// Problem constants
#define BB 2
#define SS 2048
#define HH 2048
#define NH 16
#define HD 128
#define SCALE 0.08838834764831845f  // 1/sqrt(128)

// ---------------- scratch (device globals; no allocation allowed) ----------
__device__ float g_q[(size_t)BB * NH * SS * HD];
__device__ float g_k[(size_t)BB * NH * SS * HD];
__device__ float g_v[(size_t)BB * NH * SS * HD];
__device__ float g_att[(size_t)BB * SS * HH];

// ---------------- shared mma helpers (validated in round 8) ----------------
__device__ __forceinline__ uint32_t tf32_hi_bits(float x) {
    return __float_as_uint(x) & 0xFFFFE000u;
}
__device__ __forceinline__ void split_tf32(float f, uint32_t& h, uint32_t& l) {
    h = tf32_hi_bits(f);
    l = tf32_hi_bits(f - __uint_as_float(h));
}
__device__ __forceinline__ void mma_tf32(float* c,
                                         const uint32_t* a,
                                         const uint32_t* b) {
    asm volatile(
        "mma.sync.aligned.m16n8k8.row.col.f32.tf32.tf32.f32 "
        "{%0,%1,%2,%3}, {%4,%5,%6,%7}, {%8,%9}, {%0,%1,%2,%3};"
        : "+f"(c[0]), "+f"(c[1]), "+f"(c[2]), "+f"(c[3])
        : "r"(a[0]), "r"(a[1]), "r"(a[2]), "r"(a[3]),
          "r"(b[0]), "r"(b[1]));
}

// ---------------- 3xTF32 tensor-core GEMM (unchanged, validated) -----------
#define BKT_G 16
#define SPITCH 20

template <int MODE>
__device__ __forceinline__ void gemm_tf32_body(const float* __restrict__ A,
                                               const float* __restrict__ W,
                                               float* __restrict__ C,
                                               int K, int N) {
    __shared__ float As[2][128][SPITCH];
    __shared__ float Ws[2][128][SPITCH];

    const int bn = blockIdx.x;
    const int bm = blockIdx.y;
    const int t  = threadIdx.x;
    const int wid  = t >> 5;
    const int lane = t & 31;
    const int g  = lane >> 2;
    const int tg = lane & 3;

    const int wm = (wid & 1) * 64;
    const int wn = (wid >> 1) * 32;

    const float* Ablk = A + (size_t)(bm * 128) * K;
    const float* Wblk = W + (size_t)(bn * 128) * K;

    const int r0 = t >> 2;
    const int q0 = (t & 3) * 4;
    const int r1 = (t + 256) >> 2;
    const int q1 = (t & 3) * 4;

    float acc[4][4][4];
#pragma unroll
    for (int i = 0; i < 4; i++)
#pragma unroll
        for (int j = 0; j < 4; j++)
#pragma unroll
            for (int r = 0; r < 4; r++) acc[i][j][r] = 0.f;

    {
        float4 a0 = *(const float4*)(Ablk + (size_t)r0 * K + q0);
        float4 a1 = *(const float4*)(Ablk + (size_t)r1 * K + q1);
        float4 w0 = *(const float4*)(Wblk + (size_t)r0 * K + q0);
        float4 w1 = *(const float4*)(Wblk + (size_t)r1 * K + q1);
        *(float4*)&As[0][r0][q0] = a0;
        *(float4*)&As[0][r1][q1] = a1;
        *(float4*)&Ws[0][r0][q0] = w0;
        *(float4*)&Ws[0][r1][q1] = w1;
    }
    __syncthreads();

    int buf = 0;
    for (int kt = 0; kt < K; kt += BKT_G) {
        const bool has_next = (kt + BKT_G) < K;
        float4 pa0, pa1, pw0, pw1;
        if (has_next) {
            pa0 = *(const float4*)(Ablk + (size_t)r0 * K + kt + BKT_G + q0);
            pa1 = *(const float4*)(Ablk + (size_t)r1 * K + kt + BKT_G + q1);
            pw0 = *(const float4*)(Wblk + (size_t)r0 * K + kt + BKT_G + q0);
            pw1 = *(const float4*)(Wblk + (size_t)r1 * K + kt + BKT_G + q1);
        }

#pragma unroll
        for (int k0 = 0; k0 < BKT_G; k0 += 8) {
            uint32_t Ah[4][4], Al[4][4];
            uint32_t Bh[4][2], Bl[4][2];

#pragma unroll
            for (int i = 0; i < 4; i++) {
                int row = wm + i * 16 + g;
                float f0 = As[buf][row][k0 + tg];
                float f1 = As[buf][row + 8][k0 + tg];
                float f2 = As[buf][row][k0 + tg + 4];
                float f3 = As[buf][row + 8][k0 + tg + 4];
                split_tf32(f0, Ah[i][0], Al[i][0]);
                split_tf32(f1, Ah[i][1], Al[i][1]);
                split_tf32(f2, Ah[i][2], Al[i][2]);
                split_tf32(f3, Ah[i][3], Al[i][3]);
            }
#pragma unroll
            for (int j = 0; j < 4; j++) {
                int col = wn + j * 8 + g;
                float f0 = Ws[buf][col][k0 + tg];
                float f1 = Ws[buf][col][k0 + tg + 4];
                split_tf32(f0, Bh[j][0], Bl[j][0]);
                split_tf32(f1, Bh[j][1], Bl[j][1]);
            }

#pragma unroll
            for (int i = 0; i < 4; i++)
#pragma unroll
                for (int j = 0; j < 4; j++) {
                    mma_tf32(acc[i][j], Ah[i], Bh[j]);
                    mma_tf32(acc[i][j], Ah[i], Bl[j]);
                    mma_tf32(acc[i][j], Al[i], Bh[j]);
                }
        }

        if (has_next) {
            int nb = buf ^ 1;
            *(float4*)&As[nb][r0][q0] = pa0;
            *(float4*)&As[nb][r1][q1] = pa1;
            *(float4*)&Ws[nb][r0][q0] = pw0;
            *(float4*)&Ws[nb][r1][q1] = pw1;
            __syncthreads();
        }
        buf ^= 1;
    }

#pragma unroll
    for (int i = 0; i < 4; i++) {
#pragma unroll
        for (int j = 0; j < 4; j++) {
            int m0 = bm * 128 + wm + i * 16 + g;
            int n0 = bn * 128 + wn + j * 8 + tg * 2;
#pragma unroll
            for (int r = 0; r < 4; r++) {
                int m = m0 + (r >> 1) * 8;
                int n = n0 + (r & 1);
                if (MODE == 0) {
                    int b  = m >> 11;
                    int s  = m & (SS - 1);
                    int nh = n >> 7;
                    int hd = n & (HD - 1);
                    size_t o = ((((size_t)b * NH + nh) << 11) + s) * HD + hd;
                    C[o] = acc[i][j][r];
                } else {
                    C[(size_t)m * N + n] = acc[i][j][r];
                }
            }
        }
    }
}

__global__ void __launch_bounds__(256) sgemm_qkv(
    const float* __restrict__ A,
    const float* __restrict__ Wq, const float* __restrict__ Wk,
    const float* __restrict__ Wv,
    float* __restrict__ q, float* __restrict__ k, float* __restrict__ v) {
    const float* W = (blockIdx.z == 0) ? Wq : (blockIdx.z == 1) ? Wk : Wv;
    float* C       = (blockIdx.z == 0) ? q  : (blockIdx.z == 1) ? k  : v;
    gemm_tf32_body<0>(A, W, C, HH, HH);
}

__global__ void __launch_bounds__(256) sgemm_out(
    const float* __restrict__ A, const float* __restrict__ W,
    float* __restrict__ C) {
    gemm_tf32_body<1>(A, W, C, HH, HH);
}

// ---------------- RoPE (unchanged) -----------------------------------------
__global__ void __launch_bounds__(256) rope_kernel(
    float* __restrict__ q, float* __restrict__ k,
    const float* __restrict__ cosp, const float* __restrict__ sinp) {
    const int total = BB * NH * SS * (HD / 2);
    int idx = blockIdx.x * blockDim.x + threadIdx.x;
    float* ptr = q;
    if (idx >= total) { idx -= total; ptr = k; }
    if (idx >= total) return;

    int hd = idx & 63;
    int ro = idx >> 6;
    int s  = ro & (SS - 1);
    size_t base = (size_t)ro * HD;

    float x1 = ptr[base + hd];
    float x2 = ptr[base + hd + 64];
    float c1 = cosp[s * HD + hd];
    float s1 = sinp[s * HD + hd];
    float c2 = cosp[s * HD + hd + 64];
    float s2 = sinp[s * HD + hd + 64];
    ptr[base + hd]      = x1 * c1 - x2 * s1;
    ptr[base + hd + 64] = x2 * c2 + x1 * s2;
}

// ---------------- Tensorized flash attention (3xTF32 mma) ------------------
// CTA: 128 q-rows, tiles of 64 k-cols. 8 warps; warp w owns S/O rows
// [16w, 16w+16): QK^T = 1x8 m16n8 tiles, PV = 1x16 m16n8 tiles.
// V stored transposed (Vt[d][kk]) so PV is the same NT fragment pattern.
// P round-trips through smem rows owned by the same warp (syncwarp only).
#define BQF 128
#define BKF 64
#define QP  132
#define VP  68
#define PP  68
#define SM_QS 0
#define SM_KS (BQF * QP)
#define SM_VT (SM_KS + BKF * QP)
#define SM_PS (SM_VT + HD * VP)
#define FLASH2_SMEM ((SM_PS + BQF * PP) * 4)

__global__ void __launch_bounds__(256, 1) flash_mma_kernel(
    const float* __restrict__ q, const float* __restrict__ k,
    const float* __restrict__ v, float* __restrict__ out) {
    extern __shared__ float sm[];
    float* Qs = sm + SM_QS;   // [128][132]
    float* Ks = sm + SM_KS;   // [64][132]
    float* Vt = sm + SM_VT;   // [128][68]  (row d, col kk)
    float* Ps = sm + SM_PS;   // [128][68]

    const int qt = (SS / BQF - 1) - blockIdx.x;   // heavy tiles first
    const int nh = blockIdx.y;
    const int b  = blockIdx.z;
    const int bh = b * NH + nh;
    const float* qb = q + (size_t)bh * SS * HD;
    const float* kb = k + (size_t)bh * SS * HD;
    const float* vb = v + (size_t)bh * SS * HD;

    const int tid  = threadIdx.x;
    const int wid  = tid >> 5;
    const int lane = tid & 31;
    const int g  = lane >> 2;
    const int tg = lane & 3;
    const int r0 = wid * 16 + g;        // local row (also r0+8)
    const int qg0 = qt * BQF + r0;
    const int qg1 = qg0 + 8;

    // load Q tile
    for (int i = tid; i < BQF * (HD / 4); i += 256) {
        int row = i >> 5, c4 = i & 31;
        *(float4*)&Qs[row * QP + c4 * 4] =
            ((const float4*)(qb + (size_t)(qt * BQF + row) * HD))[c4];
    }

    float o[16][4];
#pragma unroll
    for (int j = 0; j < 16; j++)
#pragma unroll
        for (int r = 0; r < 4; r++) o[j][r] = 0.f;
    float m0 = -INFINITY, m1 = -INFINITY, l0 = 0.f, l1 = 0.f;

    const int nkt = 2 * qt + 2;
    for (int kt = 0; kt < nkt; ++kt) {
        __syncthreads();   // previous tile's mma reads done before overwrite
        for (int i = tid; i < BKF * (HD / 4); i += 256) {
            int row = i >> 5, c4 = i & 31;
            *(float4*)&Ks[row * QP + c4 * 4] =
                ((const float4*)(kb + (size_t)(kt * BKF + row) * HD))[c4];
            float4 v4 = ((const float4*)(vb + (size_t)(kt * BKF + row) * HD))[c4];
            Vt[(c4 * 4 + 0) * VP + row] = v4.x;
            Vt[(c4 * 4 + 1) * VP + row] = v4.y;
            Vt[(c4 * 4 + 2) * VP + row] = v4.z;
            Vt[(c4 * 4 + 3) * VP + row] = v4.w;
        }
        __syncthreads();

        // ---- S = Q K^T (warp rows r0..r0+15, cols 0..63) ----
        float s[8][4];
#pragma unroll
        for (int j = 0; j < 8; j++)
#pragma unroll
            for (int r = 0; r < 4; r++) s[j][r] = 0.f;

        for (int k0 = 0; k0 < HD; k0 += 8) {
            uint32_t Ah[4], Al[4];
            split_tf32(Qs[r0 * QP + k0 + tg],           Ah[0], Al[0]);
            split_tf32(Qs[(r0 + 8) * QP + k0 + tg],     Ah[1], Al[1]);
            split_tf32(Qs[r0 * QP + k0 + tg + 4],       Ah[2], Al[2]);
            split_tf32(Qs[(r0 + 8) * QP + k0 + tg + 4], Ah[3], Al[3]);
#pragma unroll
            for (int nj = 0; nj < 8; nj++) {
                uint32_t Bh[2], Bl[2];
                split_tf32(Ks[(nj * 8 + g) * QP + k0 + tg],     Bh[0], Bl[0]);
                split_tf32(Ks[(nj * 8 + g) * QP + k0 + tg + 4], Bh[1], Bl[1]);
                mma_tf32(s[nj], Ah, Bh);
                mma_tf32(s[nj], Ah, Bl);
                mma_tf32(s[nj], Al, Bh);
            }
        }

        // ---- online softmax (rows qg0 via s[.][0..1], qg1 via s[.][2..3]) --
        const int colbase = kt * BKF + tg * 2;
        float rm0 = -INFINITY, rm1 = -INFINITY;
#pragma unroll
        for (int nj = 0; nj < 8; nj++) {
#pragma unroll
            for (int e = 0; e < 2; e++) {
                int c = colbase + nj * 8 + e;
                float v0 = s[nj][e] * SCALE;
                if (c > qg0) v0 = -INFINITY;
                s[nj][e] = v0;
                rm0 = fmaxf(rm0, v0);
                float v1 = s[nj][2 + e] * SCALE;
                if (c > qg1) v1 = -INFINITY;
                s[nj][2 + e] = v1;
                rm1 = fmaxf(rm1, v1);
            }
        }
        rm0 = fmaxf(rm0, __shfl_xor_sync(0xffffffffu, rm0, 1));
        rm0 = fmaxf(rm0, __shfl_xor_sync(0xffffffffu, rm0, 2));
        rm1 = fmaxf(rm1, __shfl_xor_sync(0xffffffffu, rm1, 1));
        rm1 = fmaxf(rm1, __shfl_xor_sync(0xffffffffu, rm1, 2));

        float mn0 = fmaxf(m0, rm0), mn1 = fmaxf(m1, rm1);
        float cr0 = __expf(m0 - mn0), cr1 = __expf(m1 - mn1);
        float rs0 = 0.f, rs1 = 0.f;
#pragma unroll
        for (int nj = 0; nj < 8; nj++) {
            float p0 = __expf(s[nj][0] - mn0);
            float p1 = __expf(s[nj][1] - mn0);
            float p2 = __expf(s[nj][2] - mn1);
            float p3 = __expf(s[nj][3] - mn1);
            rs0 += p0 + p1;
            rs1 += p2 + p3;
            *(float2*)&Ps[r0 * PP + nj * 8 + 2 * tg]       = make_float2(p0, p1);
            *(float2*)&Ps[(r0 + 8) * PP + nj * 8 + 2 * tg] = make_float2(p2, p3);
        }
        rs0 += __shfl_xor_sync(0xffffffffu, rs0, 1);
        rs0 += __shfl_xor_sync(0xffffffffu, rs0, 2);
        rs1 += __shfl_xor_sync(0xffffffffu, rs1, 1);
        rs1 += __shfl_xor_sync(0xffffffffu, rs1, 2);
        l0 = l0 * cr0 + rs0;
        l1 = l1 * cr1 + rs1;
        m0 = mn0; m1 = mn1;
#pragma unroll
        for (int j = 0; j < 16; j++) {
            o[j][0] *= cr0; o[j][1] *= cr0;
            o[j][2] *= cr1; o[j][3] *= cr1;
        }
        __syncwarp();   // Ps rows are warp-private; make cross-lane writes visible

        // ---- O += P V (warp rows r0..r0+15, all 128 d-cols) ----
        for (int k0 = 0; k0 < BKF; k0 += 8) {
            uint32_t Ah[4], Al[4];
            split_tf32(Ps[r0 * PP + k0 + tg],           Ah[0], Al[0]);
            split_tf32(Ps[(r0 + 8) * PP + k0 + tg],     Ah[1], Al[1]);
            split_tf32(Ps[r0 * PP + k0 + tg + 4],       Ah[2], Al[2]);
            split_tf32(Ps[(r0 + 8) * PP + k0 + tg + 4], Ah[3], Al[3]);
#pragma unroll
            for (int nj = 0; nj < 16; nj++) {
                uint32_t Bh[2], Bl[2];
                split_tf32(Vt[(nj * 8 + g) * VP + k0 + tg],     Bh[0], Bl[0]);
                split_tf32(Vt[(nj * 8 + g) * VP + k0 + tg + 4], Bh[1], Bl[1]);
                mma_tf32(o[nj], Ah, Bh);
                mma_tf32(o[nj], Ah, Bl);
                mma_tf32(o[nj], Al, Bh);
            }
        }
    }

    // ---- normalize + write (B, S, H) ----
    float il0 = 1.0f / l0, il1 = 1.0f / l1;
    float* ob0 = out + ((size_t)(b * SS + qg0)) * HH + nh * HD;
    float* ob1 = out + ((size_t)(b * SS + qg1)) * HH + nh * HD;
#pragma unroll
    for (int nj = 0; nj < 16; nj++) {
        *(float2*)&ob0[nj * 8 + 2 * tg] = make_float2(o[nj][0] * il0, o[nj][1] * il0);
        *(float2*)&ob1[nj * 8 + 2 * tg] = make_float2(o[nj][2] * il1, o[nj][3] * il1);
    }
}

// ---------------- launch ---------------------------------------------------
extern "C" void kernel_launch(void* const* d_in, const int* in_sizes, int n_in,
                              void* d_out, int out_size) {
    const float* hs   = (const float*)d_in[0];
    const float* cosp = (const float*)d_in[1];
    const float* sinp = (const float*)d_in[2];
    const float* Wq   = (const float*)d_in[3];
    const float* Wk   = (const float*)d_in[4];
    const float* Wv   = (const float*)d_in[5];
    const float* Wo   = (const float*)d_in[6];
    float* out = (float*)d_out;

    float *qp, *kp, *vp, *ap;
    cudaGetSymbolAddress((void**)&qp, g_q);
    cudaGetSymbolAddress((void**)&kp, g_k);
    cudaGetSymbolAddress((void**)&vp, g_v);
    cudaGetSymbolAddress((void**)&ap, g_att);

    // 1) QKV projections (fused over grid.z)
    dim3 pg(HH / 128, (BB * SS) / 128, 3);
    sgemm_qkv<<<pg, 256>>>(hs, Wq, Wk, Wv, qp, kp, vp);

    // 2) RoPE on q and k
    int pairs = 2 * BB * NH * SS * (HD / 2);
    rope_kernel<<<(pairs + 255) / 256, 256>>>(qp, kp, cosp, sinp);

    // 3) causal flash attention (tensor cores)
    cudaFuncSetAttribute(flash_mma_kernel,
                         cudaFuncAttributeMaxDynamicSharedMemorySize,
                         FLASH2_SMEM);
    dim3 fg(SS / BQF, NH, BB);
    flash_mma_kernel<<<fg, 256, FLASH2_SMEM>>>(qp, kp, vp, ap);

    // 4) output projection
    dim3 og(HH / 128, (BB * SS) / 128, 1);
    sgemm_out<<<og, 256>>>(ap, Wo, out);
}